// round 12
// baseline (speedup 1.0000x reference)
#include <cuda_runtime.h>
#include <stdint.h>

// out[i, 0:8] = params[idx[i]] * xs[i, 0:8]
// xs: float32 [N, 8]; idx: int32 [N]; params: float32 [V]; out: float32 [N, 8]
// N = 4194304, V = 1048576.
//
// Plateau structure (best across 10 variants): direct LDG/STG, 2 threads per
// row -> dense 16B lane-contiguous streaming wavefronts; lane pairs broadcast
// the idx/param access; gather is L2-only (__ldcg, table L2-resident).
// This round's single delta: write-THROUGH stores (__stwt) so the 128 MB
// output stream doesn't occupy L2 lines at all, freeing LTS for the gather.

#define N_ROWS  4194304
#define ITEMS   (2 * N_ROWS)                   // 8M float4 half-rows
#define UNROLL  4
#define THREADS 256
#define BLOCKS  (ITEMS / (UNROLL * THREADS))   // 8192

__global__ __launch_bounds__(THREADS) void gather_mul_kernel(
    const float4* __restrict__ xs,     // [ITEMS]
    const int*    __restrict__ idx,    // [N] int32
    const float*  __restrict__ params, // [V]
    float4*       __restrict__ out)    // [ITEMS]
{
    const int t = blockIdx.x * THREADS + threadIdx.x;
    const int S = BLOCKS * THREADS;    // 2M items per sweep

    // 1) Batch index loads (lane pairs share an address -> broadcast).
    int j[UNROLL];
#pragma unroll
    for (int k = 0; k < UNROLL; k++)
        j[k] = __ldcs(idx + ((t + k * S) >> 1));

    // 2) Batch param gathers: L2-only, table is L2-resident.
    float p[UNROLL];
#pragma unroll
    for (int k = 0; k < UNROLL; k++)
        p[k] = __ldcg(params + j[k]);

    // 3) Batch xs half-row loads: 16B lane-contiguous, evict-first.
    float4 x[UNROLL];
#pragma unroll
    for (int k = 0; k < UNROLL; k++)
        x[k] = __ldcs(xs + t + k * S);

    // 4) Multiply + write-through streaming stores (no L2 line occupancy).
#pragma unroll
    for (int k = 0; k < UNROLL; k++) {
        float4 o;
        o.x = p[k] * x[k].x;
        o.y = p[k] * x[k].y;
        o.z = p[k] * x[k].z;
        o.w = p[k] * x[k].w;
        __stwt(out + t + k * S, o);
    }
}

extern "C" void kernel_launch(void* const* d_in, const int* in_sizes, int n_in,
                              void* d_out, int out_size)
{
    const float4* xs     = (const float4*)d_in[0];
    const int*    idx    = (const int*)d_in[1];
    const float*  params = (const float*)d_in[2];
    float4*       out    = (float4*)d_out;

    gather_mul_kernel<<<BLOCKS, THREADS>>>(xs, idx, params, out);
}

// round 13
// speedup vs baseline: 1.0442x; 1.0442x over previous
#include <cuda_runtime.h>
#include <stdint.h>

// out[i, 0:8] = params[idx[i]] * xs[i, 0:8]
// xs: float32 [N, 8]; idx: int32 [N]; params: float32 [V]; out: float32 [N, 8]
// N = 4194304, V = 1048576.
//
// FINAL kernel — best measured across 11 variants (43.1 us, 5.65 TB/s, 71%
// of spec HBM). Structure: direct LDG/STG, 2 threads per row so every
// streaming access is a dense 16B lane-contiguous wavefront; lane pairs
// broadcast the idx/param access. Streams evict-first (__ldcs/__stcs) keep
// the 4 MB param table L2-resident; the gather is L2-only (__ldcg, no L1
// reuse). Proven non-binding: occupancy, deeper unroll, DRAM page layout,
// L2 pinning. Proven worse: TMA/smem staging (-30..65%), write-through
// stores (-3%). Remaining gap to spec BW is irreducible gather wavefronts +
// mixed read/write/random-sector DRAM scheduling.

#define N_ROWS  4194304
#define ITEMS   (2 * N_ROWS)                   // 8M float4 half-rows
#define UNROLL  4
#define THREADS 256
#define BLOCKS  (ITEMS / (UNROLL * THREADS))   // 8192

__global__ __launch_bounds__(THREADS) void gather_mul_kernel(
    const float4* __restrict__ xs,     // [ITEMS]
    const int*    __restrict__ idx,    // [N] int32
    const float*  __restrict__ params, // [V]
    float4*       __restrict__ out)    // [ITEMS]
{
    const int t = blockIdx.x * THREADS + threadIdx.x;
    const int S = BLOCKS * THREADS;    // 2M items per sweep

    // 1) Batch index loads (lane pairs share an address -> broadcast).
    int j[UNROLL];
#pragma unroll
    for (int k = 0; k < UNROLL; k++)
        j[k] = __ldcs(idx + ((t + k * S) >> 1));

    // 2) Batch param gathers: L2-only, table is L2-resident.
    float p[UNROLL];
#pragma unroll
    for (int k = 0; k < UNROLL; k++)
        p[k] = __ldcg(params + j[k]);

    // 3) Batch xs half-row loads: 16B lane-contiguous, evict-first.
    float4 x[UNROLL];
#pragma unroll
    for (int k = 0; k < UNROLL; k++)
        x[k] = __ldcs(xs + t + k * S);

    // 4) Multiply + streaming stores (evict-first).
#pragma unroll
    for (int k = 0; k < UNROLL; k++) {
        float4 o;
        o.x = p[k] * x[k].x;
        o.y = p[k] * x[k].y;
        o.z = p[k] * x[k].z;
        o.w = p[k] * x[k].w;
        __stcs(out + t + k * S, o);
    }
}

extern "C" void kernel_launch(void* const* d_in, const int* in_sizes, int n_in,
                              void* d_out, int out_size)
{
    const float4* xs     = (const float4*)d_in[0];
    const int*    idx    = (const int*)d_in[1];
    const float*  params = (const float*)d_in[2];
    float4*       out    = (float4*)d_out;

    gather_mul_kernel<<<BLOCKS, THREADS>>>(xs, idx, params, out);
}